// round 7
// baseline (speedup 1.0000x reference)
#include <cuda_runtime.h>

#define NN 50000
#define EE 800000

// ---------------- device scratch (static allocation: allowed) ----------------
__device__ float g_h1[NN * 256];
__device__ float g_h2[NN * 256];
__device__ float g_agg[NN * 256];
__device__ float g_Wt[256 * 256];
__device__ float g_w[EE];        // thresholded sim per edge (CSR order)
__device__ float g_rowsum[NN];
__device__ float g_wself[NN];
__device__ float g_nrm[NN];
__device__ int   g_rowptr[NN + 1];
__device__ int   g_cnt[NN];
__device__ int   g_colS[EE];

// ---------------- f32x2 packed-FMA helpers (sm_100+) ----------------
__device__ __forceinline__ void ffma2(unsigned long long& d,
                                      unsigned long long a,
                                      unsigned long long b) {
    asm("fma.rn.f32x2 %0, %1, %2, %0;" : "+l"(d) : "l"(a), "l"(b));
}
__device__ __forceinline__ unsigned long long splat2(float v) {
    unsigned long long r;
    asm("mov.b64 %0, {%1, %1};" : "=l"(r) : "f"(v));
    return r;
}
__device__ __forceinline__ float2 unpack2(unsigned long long v) {
    float2 r;
    asm("mov.b64 {%0, %1}, %2;" : "=f"(r.x), "=f"(r.y) : "l"(v));
    return r;
}

// ---------------- CSR construction ----------------
__global__ void k_zero_cnt() {
    int i = blockIdx.x * blockDim.x + threadIdx.x;
    if (i < NN) g_cnt[i] = 0;
}

__global__ void k_hist(const int* __restrict__ row) {
    int i = blockIdx.x * blockDim.x + threadIdx.x;
    if (i < EE) atomicAdd(&g_cnt[row[i]], 1);
}

// Single-block full exclusive scan of g_cnt -> g_rowptr, re-zeroing g_cnt.
__global__ void k_scan_all() {
    __shared__ int sums[1024];
    const int CH = (NN + 1023) / 1024;    // 49
    int t = threadIdx.x;
    int base = t * CH;
    int s = 0;
    for (int i = 0; i < CH; i++) {
        int idx = base + i;
        if (idx < NN) s += g_cnt[idx];
    }
    sums[t] = s;
    __syncthreads();
    for (int off = 1; off < 1024; off <<= 1) {
        int add = (t >= off) ? sums[t - off] : 0;
        __syncthreads();
        sums[t] += add;
        __syncthreads();
    }
    int run = sums[t] - s;                // exclusive prefix for this chunk
    for (int i = 0; i < CH; i++) {
        int idx = base + i;
        if (idx < NN) {
            int c = g_cnt[idx];
            g_rowptr[idx] = run;
            run += c;
            g_cnt[idx] = 0;               // ready for scatter
        }
    }
    if (t == 0) g_rowptr[NN] = EE;
}

__global__ void k_scatter(const int* __restrict__ row, const int* __restrict__ col) {
    int i = blockIdx.x * blockDim.x + threadIdx.x;
    if (i < EE) {
        int r = row[i];
        int pos = g_rowptr[r] + atomicAdd(&g_cnt[r], 1);
        g_colS[pos] = col[i];
    }
}

// ---------------- per-layer kernels (warp per node) ----------------
// NV4 = D/128 float4 per lane (D=128 -> 1, D=256 -> 2)

template <int NV4>
__global__ void k_norm(const float* __restrict__ x) {
    int n = (blockIdx.x * blockDim.x + threadIdx.x) >> 5;
    int lane = threadIdx.x & 31;
    if (n >= NN) return;
    const float4* x4 = (const float4*)x;
    float ss = 0.f;
#pragma unroll
    for (int k = 0; k < NV4; k++) {
        float4 v = x4[n * (32 * NV4) + lane + 32 * k];
        ss += v.x * v.x + v.y * v.y + v.z * v.z + v.w * v.w;
    }
#pragma unroll
    for (int o = 16; o > 0; o >>= 1) ss += __shfl_xor_sync(0xffffffffu, ss, o);
    if (lane == 0) g_nrm[n] = fmaxf(sqrtf(ss), 1e-12f);
}

// FUSED: edge cos-sim + threshold + rowsum/deg + weighted aggregation.
// Warp per node; x[row] stays in registers across both passes; live edges
// cached in smem (cap 64/warp; overflow falls back to g_w re-scan).
#define LCAP 64
template <int NV4>
__global__ void k_simagg(const float* __restrict__ x, float* __restrict__ aggx) {
    __shared__ float s_sim[8][LCAP];
    __shared__ int   s_col[8][LCAP];
    int wid = threadIdx.x >> 5;           // warp in block (blockDim=256)
    int n = (blockIdx.x * blockDim.x + threadIdx.x) >> 5;
    int lane = threadIdx.x & 31;
    if (n >= NN) return;
    const float4* x4 = (const float4*)x;
    float4 xr[NV4];
#pragma unroll
    for (int k = 0; k < NV4; k++) xr[k] = x4[n * (32 * NV4) + lane + 32 * k];
    float inv_r = 1.0f / g_nrm[n];
    int beg = g_rowptr[n], end = g_rowptr[n + 1];

    // ---- pass 1: sims ----
    float rowsum = 0.f, deg = 0.f;
    int nlive = 0;
    for (int pos = beg; pos < end; pos++) {
        int c = g_colS[pos];
        float acc = 0.f;
#pragma unroll
        for (int k = 0; k < NV4; k++) {
            float4 xc = __ldg(&x4[c * (32 * NV4) + lane + 32 * k]);
            acc += xr[k].x * xc.x + xr[k].y * xc.y + xr[k].z * xc.z + xr[k].w * xc.w;
        }
#pragma unroll
        for (int o = 16; o > 0; o >>= 1) acc += __shfl_xor_sync(0xffffffffu, acc, o);
        float sim = acc * inv_r / g_nrm[c];
        sim = (sim < 0.1f) ? 0.f : sim;     // SIM_THRESH
        if (lane == 0) g_w[pos] = sim;      // needed only for overflow path
        if (sim > 0.f) {
            if (nlive < LCAP && lane == 0) {
                s_sim[wid][nlive] = sim;
                s_col[wid][nlive] = c;
            }
            nlive++;                        // warp-uniform
            rowsum += sim;
            deg += 1.f;
        }
    }
    float ws = expf(1.0f / (deg + 1.0f));
    float inv_rs = (rowsum > 0.f) ? 1.0f / rowsum : 0.f;
    __syncwarp();

    // ---- pass 2: aggregate ----
    float4 acc[NV4];
#pragma unroll
    for (int k = 0; k < NV4; k++) {
        acc[k].x = ws * xr[k].x; acc[k].y = ws * xr[k].y;
        acc[k].z = ws * xr[k].z; acc[k].w = ws * xr[k].w;
    }
    if (nlive <= LCAP) {
        for (int i = 0; i < nlive; i++) {
            float wv = expf(s_sim[wid][i] * inv_rs);
            int c = s_col[wid][i];
#pragma unroll
            for (int k = 0; k < NV4; k++) {
                float4 xc = __ldg(&x4[c * (32 * NV4) + lane + 32 * k]);
                acc[k].x += wv * xc.x; acc[k].y += wv * xc.y;
                acc[k].z += wv * xc.z; acc[k].w += wv * xc.w;
            }
        }
    } else {
        for (int pos = beg; pos < end; pos++) {
            float sv = g_w[pos];
            if (sv > 0.f) {
                float wv = expf(sv * inv_rs);
                int c = g_colS[pos];
#pragma unroll
                for (int k = 0; k < NV4; k++) {
                    float4 xc = __ldg(&x4[c * (32 * NV4) + lane + 32 * k]);
                    acc[k].x += wv * xc.x; acc[k].y += wv * xc.y;
                    acc[k].z += wv * xc.z; acc[k].w += wv * xc.w;
                }
            }
        }
    }
    float4* a4 = (float4*)aggx;
#pragma unroll
    for (int k = 0; k < NV4; k++) a4[n * (32 * NV4) + lane + 32 * k] = acc[k];
}

// Edge cos-sim only (layer 2: aggregation happens after projection)
template <int NV4>
__global__ void k_sim(const float* __restrict__ x) {
    int n = (blockIdx.x * blockDim.x + threadIdx.x) >> 5;
    int lane = threadIdx.x & 31;
    if (n >= NN) return;
    const float4* x4 = (const float4*)x;
    float4 xr[NV4];
#pragma unroll
    for (int k = 0; k < NV4; k++) xr[k] = x4[n * (32 * NV4) + lane + 32 * k];
    float inv_r = 1.0f / g_nrm[n];
    int beg = g_rowptr[n], end = g_rowptr[n + 1];
    float rowsum = 0.f, deg = 0.f;
    for (int pos = beg; pos < end; pos++) {
        int c = g_colS[pos];
        float acc = 0.f;
#pragma unroll
        for (int k = 0; k < NV4; k++) {
            float4 xc = __ldg(&x4[c * (32 * NV4) + lane + 32 * k]);
            acc += xr[k].x * xc.x + xr[k].y * xc.y + xr[k].z * xc.z + xr[k].w * xc.w;
        }
#pragma unroll
        for (int o = 16; o > 0; o >>= 1) acc += __shfl_xor_sync(0xffffffffu, acc, o);
        float sim = acc * inv_r / g_nrm[c];
        sim = (sim < 0.1f) ? 0.f : sim;     // SIM_THRESH
        if (lane == 0) g_w[pos] = sim;
        rowsum += sim;
        deg += (sim > 0.f) ? 1.f : 0.f;
    }
    if (lane == 0) {
        g_rowsum[n] = rowsum;
        g_wself[n] = expf(1.0f / (deg + 1.0f));
    }
}

// Layer-2 aggregation in output space (F=16): 16 threads per node
__global__ void k_agg_out(const float* __restrict__ z, float* __restrict__ out) {
    int n = (blockIdx.x * blockDim.x + threadIdx.x) >> 4;
    int lane = threadIdx.x & 15;
    if (n >= NN) return;
    float rs = g_rowsum[n];
    float inv_rs = (rs > 0.f) ? 1.0f / rs : 0.f;
    float acc = g_wself[n] * z[n * 16 + lane];
    int beg = g_rowptr[n], end = g_rowptr[n + 1];
    for (int pos = beg; pos < end; pos++) {
        float sv = g_w[pos];
        if (sv > 0.f) acc += expf(sv * inv_rs) * __ldg(&z[g_colS[pos] * 16 + lane]);
    }
    out[n * 16 + lane] = acc;
}

// Pack W[H,D,O] into Wt[D, H*O]  (Wt[d*F + h*O+o] = W[h,d,o])
__global__ void k_packW(const float* __restrict__ W, int D, int F, int O) {
    int i = blockIdx.x * blockDim.x + threadIdx.x;
    if (i < D * F) {
        int d = i / F, f = i - d * F;
        int h = f / O, o = f - h * O;
        g_Wt[i] = W[(h * D + d) * O + o];
    }
}

// ---------------- f32x2 GEMM: C[NN,F] = A[NN,D] @ g_Wt[D,F], leaky -----------
// (R5 known-good single-buffered version)
__global__ __launch_bounds__(256, 2)
void k_gemm2(const float* __restrict__ A, float* __restrict__ C,
             int D, int F, int act) {
    __shared__ __align__(16) float As[16][132];   // transposed: As[k][m], +4 pad
    __shared__ __align__(16) float Bs[16][128];
    int t = threadIdx.x;
    int tx = t & 15, ty = t >> 4;                 // 16x16 threads, 8x8 each
    int bm = blockIdx.x * 128;
    int bn = blockIdx.y * 128;

    unsigned long long acc[4][8];
#pragma unroll
    for (int p = 0; p < 4; p++)
#pragma unroll
        for (int j = 0; j < 8; j++) acc[p][j] = 0ULL;

    for (int k0 = 0; k0 < D; k0 += 16) {
        float4 av[2], bv[2];
#pragma unroll
        for (int q = 0; q < 2; q++) {
            int v = t + q * 256;                  // 0..511
            int am = v >> 2, ak4 = (v & 3) * 4;
            int gm = bm + am;
            if (gm < NN) av[q] = *(const float4*)&A[gm * D + k0 + ak4];
            else av[q] = make_float4(0.f, 0.f, 0.f, 0.f);
            int bk = v >> 5, bc4 = (v & 31) * 4;
            bv[q] = *(const float4*)&g_Wt[(k0 + bk) * F + bn + bc4];
        }
        __syncthreads();                          // prev tile consumed
#pragma unroll
        for (int q = 0; q < 2; q++) {
            int v = t + q * 256;
            int am = v >> 2, ak4 = (v & 3) * 4;
            As[ak4 + 0][am] = av[q].x; As[ak4 + 1][am] = av[q].y;
            As[ak4 + 2][am] = av[q].z; As[ak4 + 3][am] = av[q].w;
            int bk = v >> 5, bc4 = (v & 31) * 4;
            *(float4*)&Bs[bk][bc4] = bv[q];
        }
        __syncthreads();
#pragma unroll
        for (int k = 0; k < 16; k++) {
            ulonglong2 a01 = *(const ulonglong2*)&As[k][ty * 8];
            ulonglong2 a23 = *(const ulonglong2*)&As[k][ty * 8 + 4];
            unsigned long long ap[4] = {a01.x, a01.y, a23.x, a23.y};
            float4 b0 = *(const float4*)&Bs[k][tx * 8];
            float4 b1 = *(const float4*)&Bs[k][tx * 8 + 4];
            unsigned long long bsv[8] = {
                splat2(b0.x), splat2(b0.y), splat2(b0.z), splat2(b0.w),
                splat2(b1.x), splat2(b1.y), splat2(b1.z), splat2(b1.w)};
#pragma unroll
            for (int p = 0; p < 4; p++)
#pragma unroll
                for (int j = 0; j < 8; j++) ffma2(acc[p][j], ap[p], bsv[j]);
        }
    }

    // epilogue
#pragma unroll
    for (int p = 0; p < 4; p++) {
        float2 uu[8];
#pragma unroll
        for (int j = 0; j < 8; j++) uu[j] = unpack2(acc[p][j]);
#pragma unroll
        for (int e = 0; e < 2; e++) {
            int gm = bm + ty * 8 + p * 2 + e;
            if (gm >= NN) continue;
            float r[8];
#pragma unroll
            for (int j = 0; j < 8; j++) r[j] = e ? uu[j].y : uu[j].x;
            if (act) {
#pragma unroll
                for (int j = 0; j < 8; j++) r[j] = (r[j] >= 0.f) ? r[j] : 0.01f * r[j];
            }
            float4* dst = (float4*)&C[gm * F + bn + tx * 8];
            dst[0] = make_float4(r[0], r[1], r[2], r[3]);
            dst[1] = make_float4(r[4], r[5], r[6], r[7]);
        }
    }
}

// ---------------- small fp32 GEMM for F=16 (layer 2, B = W2 directly) --------
__global__ void k_gemm(const float* __restrict__ A, const float* __restrict__ B,
                       float* __restrict__ C, int D, int F) {
    __shared__ __align__(16) float As[16][68];
    __shared__ __align__(16) float Bs[16][64];
    int t = threadIdx.x;
    int tx = t & 15, ty = t >> 4;
    int bm = blockIdx.x * 64;
    float acc[4][4];
#pragma unroll
    for (int i = 0; i < 4; i++)
#pragma unroll
        for (int j = 0; j < 4; j++) acc[i][j] = 0.f;

    int am = t >> 2, akq = (t & 3) * 4;
    int bk = t >> 4, bn4 = (t & 15) * 4;

    for (int k0 = 0; k0 < D; k0 += 16) {
        float4 av;
        int gm = bm + am;
        if (gm < NN) av = *(const float4*)&A[gm * D + k0 + akq];
        else av = make_float4(0.f, 0.f, 0.f, 0.f);
        As[akq + 0][am] = av.x; As[akq + 1][am] = av.y;
        As[akq + 2][am] = av.z; As[akq + 3][am] = av.w;

        float4 bvv;
        const float* Brow = &B[(k0 + bk) * F];
        if (bn4 + 3 < F) bvv = *(const float4*)&Brow[bn4];
        else bvv = make_float4(0.f, 0.f, 0.f, 0.f);
        *(float4*)&Bs[bk][bn4] = bvv;
        __syncthreads();
#pragma unroll
        for (int k = 0; k < 16; k++) {
            float4 a = *(const float4*)&As[k][ty * 4];
            float4 b = *(const float4*)&Bs[k][tx * 4];
            acc[0][0] += a.x * b.x; acc[0][1] += a.x * b.y; acc[0][2] += a.x * b.z; acc[0][3] += a.x * b.w;
            acc[1][0] += a.y * b.x; acc[1][1] += a.y * b.y; acc[1][2] += a.y * b.z; acc[1][3] += a.y * b.w;
            acc[2][0] += a.z * b.x; acc[2][1] += a.z * b.y; acc[2][2] += a.z * b.z; acc[2][3] += a.z * b.w;
            acc[3][0] += a.w * b.x; acc[3][1] += a.w * b.y; acc[3][2] += a.w * b.z; acc[3][3] += a.w * b.w;
        }
        __syncthreads();
    }
#pragma unroll
    for (int i = 0; i < 4; i++) {
        int gm = bm + ty * 4 + i;
        if (gm >= NN) continue;
#pragma unroll
        for (int j = 0; j < 4; j++) {
            int gn = tx * 4 + j;
            if (gn < F) C[gm * F + gn] = acc[i][j];
        }
    }
}

// ---------------- launch ----------------
extern "C" void kernel_launch(void* const* d_in, const int* in_sizes, int n_in,
                              void* d_out, int out_size) {
    const float* x  = (const float*)d_in[0];
    const float* W0 = (const float*)d_in[1];
    const float* W1 = (const float*)d_in[2];
    const float* W2 = (const float*)d_in[3];
    const int*   row = (const int*)d_in[4];
    const int*   col = (const int*)d_in[5];
    float* out = (float*)d_out;

    float *h1, *h2, *agg;
    cudaGetSymbolAddress((void**)&h1, g_h1);
    cudaGetSymbolAddress((void**)&h2, g_h2);
    cudaGetSymbolAddress((void**)&agg, g_agg);

    const int TB = 256;
    int gN = (NN + TB - 1) / TB;
    int gE = (EE + TB - 1) / TB;
    int gW = (NN * 32 + TB - 1) / TB;    // warp-per-node
    int gH = (NN * 16 + TB - 1) / TB;    // 16 threads per node

    // ---- CSR (row/col shared by all 3 layers): 4 launches ----
    k_zero_cnt<<<gN, TB>>>();
    k_hist<<<gE, TB>>>(row);
    k_scan_all<<<1, 1024>>>();
    k_scatter<<<gE, TB>>>(row, col);

    // ---- layer 0: D=128, F=256, aggregate-then-project, leaky ----
    k_norm<1><<<gW, TB>>>(x);
    k_simagg<1><<<gW, TB>>>(x, agg);
    k_packW<<<(128 * 256 + TB - 1) / TB, TB>>>(W0, 128, 256, 64);
    {
        dim3 grid((NN + 127) / 128, 2);
        k_gemm2<<<grid, 256>>>(agg, h1, 128, 256, 1);
    }

    // ---- layer 1: D=256, F=256, aggregate-then-project, leaky ----
    k_norm<2><<<gW, TB>>>(h1);
    k_simagg<2><<<gW, TB>>>(h1, agg);
    k_packW<<<(256 * 256 + TB - 1) / TB, TB>>>(W1, 256, 256, 64);
    {
        dim3 grid((NN + 127) / 128, 2);
        k_gemm2<<<grid, 256>>>(agg, h2, 256, 256, 1);
    }

    // ---- layer 2: D=256, F=16, project-then-aggregate, no act ----
    k_norm<2><<<gW, TB>>>(h2);
    k_sim<2><<<gW, TB>>>(h2);
    {
        dim3 grid((NN + 63) / 64, 1);
        k_gemm<<<grid, 256>>>(h2, W2, agg, 256, 16);   // z = h2 @ W2
    }
    k_agg_out<<<gH, TB>>>(agg, out);
}

// round 8
// speedup vs baseline: 1.0924x; 1.0924x over previous
#include <cuda_runtime.h>

#define NN 50000
#define EE 800000
#define SCAN_B 1024
#define NBLK ((NN + SCAN_B - 1) / SCAN_B)

// ---------------- device scratch (static allocation: allowed) ----------------
__device__ float g_h1[NN * 256];
__device__ float g_h2[NN * 256];
__device__ float g_agg[NN * 256];
__device__ float g_Wt[256 * 256];
__device__ float g_w[EE];        // thresholded sim per edge (CSR order)
__device__ float g_rowsum[NN];
__device__ float g_wself[NN];
__device__ float g_nrm[NN];
__device__ int   g_rowptr[NN + 1];
__device__ int   g_cnt[NN];
__device__ int   g_colS[EE];
__device__ int   g_bsum[NBLK];
__device__ int   g_boff[NBLK];

// ---------------- f32x2 packed-FMA helpers (sm_100+) ----------------
__device__ __forceinline__ void ffma2(unsigned long long& d,
                                      unsigned long long a,
                                      unsigned long long b) {
    asm("fma.rn.f32x2 %0, %1, %2, %0;" : "+l"(d) : "l"(a), "l"(b));
}
__device__ __forceinline__ unsigned long long splat2(float v) {
    unsigned long long r;
    asm("mov.b64 %0, {%1, %1};" : "=l"(r) : "f"(v));
    return r;
}
__device__ __forceinline__ float2 unpack2(unsigned long long v) {
    float2 r;
    asm("mov.b64 {%0, %1}, %2;" : "=f"(r.x), "=f"(r.y) : "l"(v));
    return r;
}

// ---------------- CSR construction (R5 coalesced multi-block scan) ----------
__global__ void k_zero_cnt() {
    int i = blockIdx.x * blockDim.x + threadIdx.x;
    if (i < NN) g_cnt[i] = 0;
}

__global__ void k_hist(const int* __restrict__ row) {
    int i = blockIdx.x * blockDim.x + threadIdx.x;
    if (i < EE) atomicAdd(&g_cnt[row[i]], 1);
}

__global__ void k_scan1() {
    __shared__ int sh[SCAN_B];
    int t = threadIdx.x;
    int i = blockIdx.x * SCAN_B + t;
    int v = (i < NN) ? g_cnt[i] : 0;
    sh[t] = v;
    __syncthreads();
    for (int off = 1; off < SCAN_B; off <<= 1) {
        int add = (t >= off) ? sh[t - off] : 0;
        __syncthreads();
        sh[t] += add;
        __syncthreads();
    }
    if (i < NN) g_rowptr[i] = sh[t] - v;   // exclusive
    if (t == SCAN_B - 1) g_bsum[blockIdx.x] = sh[t];
}

__global__ void k_scan2() {
    __shared__ int sh[64];
    int t = threadIdx.x;
    int v = (t < NBLK) ? g_bsum[t] : 0;
    sh[t] = v;
    __syncthreads();
    for (int off = 1; off < 64; off <<= 1) {
        int add = (t >= off) ? sh[t - off] : 0;
        __syncthreads();
        sh[t] += add;
        __syncthreads();
    }
    if (t < NBLK) g_boff[t] = sh[t] - v;   // exclusive
}

__global__ void k_scan3() {
    int i = blockIdx.x * blockDim.x + threadIdx.x;
    if (i < NN) g_rowptr[i] += g_boff[i >> 10];
    if (i == 0) g_rowptr[NN] = EE;
}

__global__ void k_scatter(const int* __restrict__ row, const int* __restrict__ col) {
    int i = blockIdx.x * blockDim.x + threadIdx.x;
    if (i < EE) {
        int r = row[i];
        int pos = g_rowptr[r] + atomicAdd(&g_cnt[r], 1);
        g_colS[pos] = col[i];
    }
}

// ---------------- per-layer kernels (warp per node) ----------------
// NV4 = D/128 float4 per lane (D=128 -> 1, D=256 -> 2)

template <int NV4>
__global__ void k_norm(const float* __restrict__ x) {
    int n = (blockIdx.x * blockDim.x + threadIdx.x) >> 5;
    int lane = threadIdx.x & 31;
    if (n >= NN) return;
    const float4* x4 = (const float4*)x;
    float ss = 0.f;
#pragma unroll
    for (int k = 0; k < NV4; k++) {
        float4 v = x4[n * (32 * NV4) + lane + 32 * k];
        ss += v.x * v.x + v.y * v.y + v.z * v.z + v.w * v.w;
    }
#pragma unroll
    for (int o = 16; o > 0; o >>= 1) ss += __shfl_xor_sync(0xffffffffu, ss, o);
    if (lane == 0) g_nrm[n] = fmaxf(sqrtf(ss), 1e-12f);
}

// FUSED: edge cos-sim + threshold + rowsum/deg + weighted aggregation.
// Warp per node; x[row] stays in registers across both passes; live edges
// cached in smem (cap 64/warp; overflow falls back to g_w re-scan).
#define LCAP 64
template <int NV4>
__global__ void k_simagg(const float* __restrict__ x, float* __restrict__ aggx) {
    __shared__ float s_sim[8][LCAP];
    __shared__ int   s_col[8][LCAP];
    int wid = threadIdx.x >> 5;           // warp in block (blockDim=256)
    int n = (blockIdx.x * blockDim.x + threadIdx.x) >> 5;
    int lane = threadIdx.x & 31;
    if (n >= NN) return;
    const float4* x4 = (const float4*)x;
    float4 xr[NV4];
#pragma unroll
    for (int k = 0; k < NV4; k++) xr[k] = x4[n * (32 * NV4) + lane + 32 * k];
    float inv_r = 1.0f / g_nrm[n];
    int beg = g_rowptr[n], end = g_rowptr[n + 1];

    // ---- pass 1: sims ----
    float rowsum = 0.f, deg = 0.f;
    int nlive = 0;
    for (int pos = beg; pos < end; pos++) {
        int c = g_colS[pos];
        float acc = 0.f;
#pragma unroll
        for (int k = 0; k < NV4; k++) {
            float4 xc = __ldg(&x4[c * (32 * NV4) + lane + 32 * k]);
            acc += xr[k].x * xc.x + xr[k].y * xc.y + xr[k].z * xc.z + xr[k].w * xc.w;
        }
#pragma unroll
        for (int o = 16; o > 0; o >>= 1) acc += __shfl_xor_sync(0xffffffffu, acc, o);
        float sim = acc * inv_r / g_nrm[c];
        sim = (sim < 0.1f) ? 0.f : sim;     // SIM_THRESH
        if (lane == 0) g_w[pos] = sim;      // needed only for overflow path
        if (sim > 0.f) {
            if (nlive < LCAP && lane == 0) {
                s_sim[wid][nlive] = sim;
                s_col[wid][nlive] = c;
            }
            nlive++;                        // warp-uniform
            rowsum += sim;
            deg += 1.f;
        }
    }
    float ws = expf(1.0f / (deg + 1.0f));
    float inv_rs = (rowsum > 0.f) ? 1.0f / rowsum : 0.f;
    __syncwarp();

    // ---- pass 2: aggregate ----
    float4 acc[NV4];
#pragma unroll
    for (int k = 0; k < NV4; k++) {
        acc[k].x = ws * xr[k].x; acc[k].y = ws * xr[k].y;
        acc[k].z = ws * xr[k].z; acc[k].w = ws * xr[k].w;
    }
    if (nlive <= LCAP) {
        for (int i = 0; i < nlive; i++) {
            float wv = expf(s_sim[wid][i] * inv_rs);
            int c = s_col[wid][i];
#pragma unroll
            for (int k = 0; k < NV4; k++) {
                float4 xc = __ldg(&x4[c * (32 * NV4) + lane + 32 * k]);
                acc[k].x += wv * xc.x; acc[k].y += wv * xc.y;
                acc[k].z += wv * xc.z; acc[k].w += wv * xc.w;
            }
        }
    } else {
        for (int pos = beg; pos < end; pos++) {
            float sv = g_w[pos];
            if (sv > 0.f) {
                float wv = expf(sv * inv_rs);
                int c = g_colS[pos];
#pragma unroll
                for (int k = 0; k < NV4; k++) {
                    float4 xc = __ldg(&x4[c * (32 * NV4) + lane + 32 * k]);
                    acc[k].x += wv * xc.x; acc[k].y += wv * xc.y;
                    acc[k].z += wv * xc.z; acc[k].w += wv * xc.w;
                }
            }
        }
    }
    float4* a4 = (float4*)aggx;
#pragma unroll
    for (int k = 0; k < NV4; k++) a4[n * (32 * NV4) + lane + 32 * k] = acc[k];
}

// Edge cos-sim only (layer 2: aggregation happens after projection)
template <int NV4>
__global__ void k_sim(const float* __restrict__ x) {
    int n = (blockIdx.x * blockDim.x + threadIdx.x) >> 5;
    int lane = threadIdx.x & 31;
    if (n >= NN) return;
    const float4* x4 = (const float4*)x;
    float4 xr[NV4];
#pragma unroll
    for (int k = 0; k < NV4; k++) xr[k] = x4[n * (32 * NV4) + lane + 32 * k];
    float inv_r = 1.0f / g_nrm[n];
    int beg = g_rowptr[n], end = g_rowptr[n + 1];
    float rowsum = 0.f, deg = 0.f;
    for (int pos = beg; pos < end; pos++) {
        int c = g_colS[pos];
        float acc = 0.f;
#pragma unroll
        for (int k = 0; k < NV4; k++) {
            float4 xc = __ldg(&x4[c * (32 * NV4) + lane + 32 * k]);
            acc += xr[k].x * xc.x + xr[k].y * xc.y + xr[k].z * xc.z + xr[k].w * xc.w;
        }
#pragma unroll
        for (int o = 16; o > 0; o >>= 1) acc += __shfl_xor_sync(0xffffffffu, acc, o);
        float sim = acc * inv_r / g_nrm[c];
        sim = (sim < 0.1f) ? 0.f : sim;     // SIM_THRESH
        if (lane == 0) g_w[pos] = sim;
        rowsum += sim;
        deg += (sim > 0.f) ? 1.f : 0.f;
    }
    if (lane == 0) {
        g_rowsum[n] = rowsum;
        g_wself[n] = expf(1.0f / (deg + 1.0f));
    }
}

// Layer-2 aggregation in output space (F=16): 16 threads per node
__global__ void k_agg_out(const float* __restrict__ z, float* __restrict__ out) {
    int n = (blockIdx.x * blockDim.x + threadIdx.x) >> 4;
    int lane = threadIdx.x & 15;
    if (n >= NN) return;
    float rs = g_rowsum[n];
    float inv_rs = (rs > 0.f) ? 1.0f / rs : 0.f;
    float acc = g_wself[n] * z[n * 16 + lane];
    int beg = g_rowptr[n], end = g_rowptr[n + 1];
    for (int pos = beg; pos < end; pos++) {
        float sv = g_w[pos];
        if (sv > 0.f) acc += expf(sv * inv_rs) * __ldg(&z[g_colS[pos] * 16 + lane]);
    }
    out[n * 16 + lane] = acc;
}

// Pack W[H,D,O] into Wt[D, H*O]  (Wt[d*F + h*O+o] = W[h,d,o])
__global__ void k_packW(const float* __restrict__ W, int D, int F, int O) {
    int i = blockIdx.x * blockDim.x + threadIdx.x;
    if (i < D * F) {
        int d = i / F, f = i - d * F;
        int h = f / O, o = f - h * O;
        g_Wt[i] = W[(h * D + d) * O + o];
    }
}

// ---------------- f32x2 GEMM: C[NN,F] = A[NN,D] @ g_Wt[D,F], leaky -----------
// (R5 known-good single-buffered version)
__global__ __launch_bounds__(256, 2)
void k_gemm2(const float* __restrict__ A, float* __restrict__ C,
             int D, int F, int act) {
    __shared__ __align__(16) float As[16][132];   // transposed: As[k][m], +4 pad
    __shared__ __align__(16) float Bs[16][128];
    int t = threadIdx.x;
    int tx = t & 15, ty = t >> 4;                 // 16x16 threads, 8x8 each
    int bm = blockIdx.x * 128;
    int bn = blockIdx.y * 128;

    unsigned long long acc[4][8];
#pragma unroll
    for (int p = 0; p < 4; p++)
#pragma unroll
        for (int j = 0; j < 8; j++) acc[p][j] = 0ULL;

    for (int k0 = 0; k0 < D; k0 += 16) {
        float4 av[2], bv[2];
#pragma unroll
        for (int q = 0; q < 2; q++) {
            int v = t + q * 256;                  // 0..511
            int am = v >> 2, ak4 = (v & 3) * 4;
            int gm = bm + am;
            if (gm < NN) av[q] = *(const float4*)&A[gm * D + k0 + ak4];
            else av[q] = make_float4(0.f, 0.f, 0.f, 0.f);
            int bk = v >> 5, bc4 = (v & 31) * 4;
            bv[q] = *(const float4*)&g_Wt[(k0 + bk) * F + bn + bc4];
        }
        __syncthreads();                          // prev tile consumed
#pragma unroll
        for (int q = 0; q < 2; q++) {
            int v = t + q * 256;
            int am = v >> 2, ak4 = (v & 3) * 4;
            As[ak4 + 0][am] = av[q].x; As[ak4 + 1][am] = av[q].y;
            As[ak4 + 2][am] = av[q].z; As[ak4 + 3][am] = av[q].w;
            int bk = v >> 5, bc4 = (v & 31) * 4;
            *(float4*)&Bs[bk][bc4] = bv[q];
        }
        __syncthreads();
#pragma unroll
        for (int k = 0; k < 16; k++) {
            ulonglong2 a01 = *(const ulonglong2*)&As[k][ty * 8];
            ulonglong2 a23 = *(const ulonglong2*)&As[k][ty * 8 + 4];
            unsigned long long ap[4] = {a01.x, a01.y, a23.x, a23.y};
            float4 b0 = *(const float4*)&Bs[k][tx * 8];
            float4 b1 = *(const float4*)&Bs[k][tx * 8 + 4];
            unsigned long long bsv[8] = {
                splat2(b0.x), splat2(b0.y), splat2(b0.z), splat2(b0.w),
                splat2(b1.x), splat2(b1.y), splat2(b1.z), splat2(b1.w)};
#pragma unroll
            for (int p = 0; p < 4; p++)
#pragma unroll
                for (int j = 0; j < 8; j++) ffma2(acc[p][j], ap[p], bsv[j]);
        }
    }

    // epilogue
#pragma unroll
    for (int p = 0; p < 4; p++) {
        float2 uu[8];
#pragma unroll
        for (int j = 0; j < 8; j++) uu[j] = unpack2(acc[p][j]);
#pragma unroll
        for (int e = 0; e < 2; e++) {
            int gm = bm + ty * 8 + p * 2 + e;
            if (gm >= NN) continue;
            float r[8];
#pragma unroll
            for (int j = 0; j < 8; j++) r[j] = e ? uu[j].y : uu[j].x;
            if (act) {
#pragma unroll
                for (int j = 0; j < 8; j++) r[j] = (r[j] >= 0.f) ? r[j] : 0.01f * r[j];
            }
            float4* dst = (float4*)&C[gm * F + bn + tx * 8];
            dst[0] = make_float4(r[0], r[1], r[2], r[3]);
            dst[1] = make_float4(r[4], r[5], r[6], r[7]);
        }
    }
}

// ---------------- small fp32 GEMM for F=16 (layer 2, B = W2 directly) --------
__global__ void k_gemm(const float* __restrict__ A, const float* __restrict__ B,
                       float* __restrict__ C, int D, int F) {
    __shared__ __align__(16) float As[16][68];
    __shared__ __align__(16) float Bs[16][64];
    int t = threadIdx.x;
    int tx = t & 15, ty = t >> 4;
    int bm = blockIdx.x * 64;
    float acc[4][4];
#pragma unroll
    for (int i = 0; i < 4; i++)
#pragma unroll
        for (int j = 0; j < 4; j++) acc[i][j] = 0.f;

    int am = t >> 2, akq = (t & 3) * 4;
    int bk = t >> 4, bn4 = (t & 15) * 4;

    for (int k0 = 0; k0 < D; k0 += 16) {
        float4 av;
        int gm = bm + am;
        if (gm < NN) av = *(const float4*)&A[gm * D + k0 + akq];
        else av = make_float4(0.f, 0.f, 0.f, 0.f);
        As[akq + 0][am] = av.x; As[akq + 1][am] = av.y;
        As[akq + 2][am] = av.z; As[akq + 3][am] = av.w;

        float4 bvv;
        const float* Brow = &B[(k0 + bk) * F];
        if (bn4 + 3 < F) bvv = *(const float4*)&Brow[bn4];
        else bvv = make_float4(0.f, 0.f, 0.f, 0.f);
        *(float4*)&Bs[bk][bn4] = bvv;
        __syncthreads();
#pragma unroll
        for (int k = 0; k < 16; k++) {
            float4 a = *(const float4*)&As[k][ty * 4];
            float4 b = *(const float4*)&Bs[k][tx * 4];
            acc[0][0] += a.x * b.x; acc[0][1] += a.x * b.y; acc[0][2] += a.x * b.z; acc[0][3] += a.x * b.w;
            acc[1][0] += a.y * b.x; acc[1][1] += a.y * b.y; acc[1][2] += a.y * b.z; acc[1][3] += a.y * b.w;
            acc[2][0] += a.z * b.x; acc[2][1] += a.z * b.y; acc[2][2] += a.z * b.z; acc[2][3] += a.z * b.w;
            acc[3][0] += a.w * b.x; acc[3][1] += a.w * b.y; acc[3][2] += a.w * b.z; acc[3][3] += a.w * b.w;
        }
        __syncthreads();
    }
#pragma unroll
    for (int i = 0; i < 4; i++) {
        int gm = bm + ty * 4 + i;
        if (gm >= NN) continue;
#pragma unroll
        for (int j = 0; j < 4; j++) {
            int gn = tx * 4 + j;
            if (gn < F) C[gm * F + gn] = acc[i][j];
        }
    }
}

// ---------------- launch ----------------
extern "C" void kernel_launch(void* const* d_in, const int* in_sizes, int n_in,
                              void* d_out, int out_size) {
    const float* x  = (const float*)d_in[0];
    const float* W0 = (const float*)d_in[1];
    const float* W1 = (const float*)d_in[2];
    const float* W2 = (const float*)d_in[3];
    const int*   row = (const int*)d_in[4];
    const int*   col = (const int*)d_in[5];
    float* out = (float*)d_out;

    float *h1, *h2, *agg;
    cudaGetSymbolAddress((void**)&h1, g_h1);
    cudaGetSymbolAddress((void**)&h2, g_h2);
    cudaGetSymbolAddress((void**)&agg, g_agg);

    const int TB = 256;
    int gN = (NN + TB - 1) / TB;
    int gE = (EE + TB - 1) / TB;
    int gW = (NN * 32 + TB - 1) / TB;    // warp-per-node
    int gH = (NN * 16 + TB - 1) / TB;    // 16 threads per node

    // ---- CSR (R5 coalesced pipeline) ----
    k_zero_cnt<<<gN, TB>>>();
    k_hist<<<gE, TB>>>(row);
    k_scan1<<<NBLK, SCAN_B>>>();
    k_scan2<<<1, 64>>>();
    k_scan3<<<gN, TB>>>();
    k_zero_cnt<<<gN, TB>>>();
    k_scatter<<<gE, TB>>>(row, col);

    // ---- layer 0: D=128, F=256, aggregate-then-project, leaky ----
    k_norm<1><<<gW, TB>>>(x);
    k_simagg<1><<<gW, TB>>>(x, agg);
    k_packW<<<(128 * 256 + TB - 1) / TB, TB>>>(W0, 128, 256, 64);
    {
        dim3 grid((NN + 127) / 128, 2);
        k_gemm2<<<grid, 256>>>(agg, h1, 128, 256, 1);
    }

    // ---- layer 1: D=256, F=256, aggregate-then-project, leaky ----
    k_norm<2><<<gW, TB>>>(h1);
    k_simagg<2><<<gW, TB>>>(h1, agg);
    k_packW<<<(256 * 256 + TB - 1) / TB, TB>>>(W1, 256, 256, 64);
    {
        dim3 grid((NN + 127) / 128, 2);
        k_gemm2<<<grid, 256>>>(agg, h2, 256, 256, 1);
    }

    // ---- layer 2: D=256, F=16, project-then-aggregate, no act ----
    k_norm<2><<<gW, TB>>>(h2);
    k_sim<2><<<gW, TB>>>(h2);
    {
        dim3 grid((NN + 63) / 64, 1);
        k_gemm<<<grid, 256>>>(h2, W2, agg, 256, 16);   // z = h2 @ W2
    }
    k_agg_out<<<gH, TB>>>(agg, out);
}